// round 10
// baseline (speedup 1.0000x reference)
#include <cuda_runtime.h>
#include <cstdint>

// ---------------------------------------------------------------------------
// Problem constants
// ---------------------------------------------------------------------------
#define K_TOTAL   98304      // F = 3*256*128
#define KSPLITS   74
#define M_ROWS    128        // B*N = 32*4
#define D_DIM     512
#define N_TILE    128        // N per CTA (4 quarters)

#define D_ELEMS   (32*32*3*512)        // 1572864
#define W_ELEMS   (32*32*3*3)          // 9216
#define L_ELEMS   (32*32*3)            // 3072
#define W_OFF     D_ELEMS
#define L_OFF     (D_ELEMS + W_ELEMS)

// smem (per 256-thread CTA, 2 CTAs/SM):
//   rawB fp32 triple-buffer, fA f16 quad-buffer (compact 64B rows), fB double
#define RAWB_STAGE 16384     // 32 k x 128 n fp32, 512B rows
#define FA_STAGE   8192      // 128 m x 64B rows (32 f16), 4 chunks, sw=(m&3)
#define FB_STAGE   8192      // 32 k x 128 f16, 256B rows
#define RAWB_BASE  0
#define FA_BASE    (3 * RAWB_STAGE)                 // 49152
#define FB_BASE    (FA_BASE + 4 * FA_STAGE)         // 81920
#define SMEM_TOTAL (FB_BASE + 2 * FB_STAGE)         // 98304 (96KB)

// ---------------------------------------------------------------------------
// Scratch (static __device__: no allocation allowed)
// ---------------------------------------------------------------------------
__device__ float    g_partial[(size_t)KSPLITS * M_ROWS * D_DIM]; // ~18.5 MB
__device__ float    g_e[M_ROWS * D_DIM];                         // 256 KB
__device__ uint16_t g_xh[(size_t)M_ROWS * K_TOTAL];              // 24 MB

// ---------------------------------------------------------------------------
// PTX helpers (sm_80-era: portable to sm_100 base target)
// ---------------------------------------------------------------------------
__device__ __forceinline__ uint32_t smem_u32(const void* p) {
    uint32_t a;
    asm("{ .reg .u64 t; cvta.to.shared.u64 t, %1; cvt.u32.u64 %0, t; }"
        : "=r"(a) : "l"(p));
    return a;
}

__device__ __forceinline__ void cp16(uint32_t dst, const void* src) {
    asm volatile("cp.async.cg.shared.global [%0], [%1], 16;"
                 :: "r"(dst), "l"(src) : "memory");
}
__device__ __forceinline__ void cp_commit() {
    asm volatile("cp.async.commit_group;" ::: "memory");
}
__device__ __forceinline__ void cp_wait1() {
    asm volatile("cp.async.wait_group 1;" ::: "memory");
}
__device__ __forceinline__ void cp_wait2() {
    asm volatile("cp.async.wait_group 2;" ::: "memory");
}

__device__ __forceinline__ void ldsm_x4(uint32_t* r, uint32_t a) {
    asm volatile("ldmatrix.sync.aligned.m8n8.x4.shared.b16 {%0,%1,%2,%3}, [%4];"
                 : "=r"(r[0]), "=r"(r[1]), "=r"(r[2]), "=r"(r[3]) : "r"(a));
}
__device__ __forceinline__ void ldsm_x4_t(uint32_t* r, uint32_t a) {
    asm volatile("ldmatrix.sync.aligned.m8n8.x4.trans.shared.b16 {%0,%1,%2,%3}, [%4];"
                 : "=r"(r[0]), "=r"(r[1]), "=r"(r[2]), "=r"(r[3]) : "r"(a));
}

__device__ __forceinline__ void mma16816(float* c, const uint32_t* a,
                                         const uint32_t* b) {
    asm volatile(
        "mma.sync.aligned.m16n8k16.row.col.f32.f16.f16.f32 "
        "{%0,%1,%2,%3}, {%4,%5,%6,%7}, {%8,%9}, {%0,%1,%2,%3};"
        : "+f"(c[0]), "+f"(c[1]), "+f"(c[2]), "+f"(c[3])
        : "r"(a[0]), "r"(a[1]), "r"(a[2]), "r"(a[3]), "r"(b[0]), "r"(b[1]));
}

// ---------------------------------------------------------------------------
// Kernel 0: convert x fp32 -> f16 (hi only), streaming
// ---------------------------------------------------------------------------
__global__ __launch_bounds__(256)
void convx_kernel(const float* __restrict__ x) {
    const size_t base = ((size_t)blockIdx.x * 256 + threadIdx.x) * 8;
    #pragma unroll
    for (int h = 0; h < 2; h++) {
        const size_t i = base + h * 4;
        float4 v = __ldg((const float4*)(x + i));
        uint32_t h01, h23;
        asm("cvt.rn.f16x2.f32 %0, %1, %2;" : "=r"(h01) : "f"(v.y), "f"(v.x));
        asm("cvt.rn.f16x2.f32 %0, %1, %2;" : "=r"(h23) : "f"(v.w), "f"(v.z));
        *(uint2*)(g_xh + i) = make_uint2(h01, h23);
    }
}

// ---------------------------------------------------------------------------
// Kernel 1: split-K fp16 GEMM -> partial sums
// grid = 296 CTAs: blockIdx.x = kidx*4 + nq ; 256 threads, 2 CTAs/SM
// Single-barrier pipeline; convB(s+1) overlapped under MMA(s)
// ---------------------------------------------------------------------------
__global__ __launch_bounds__(256, 2)
void gemm_split_kernel(const float* __restrict__ W) {
    extern __shared__ char smem[];
    const uint32_t sb = smem_u32(smem);
    const int tid  = threadIdx.x;
    const int wid  = tid >> 5;          // 0..7
    const int lane = tid & 31;

    const int nq   = blockIdx.x & 3;
    const int kidx = blockIdx.x >> 2;
    const int ncol0 = nq * N_TILE;
    // distribute 3072 32-wide K-steps over 74 splits: 38 CTAs get 42, rest 41
    const int nsteps = 41 + (kidx < 38 ? 1 : 0);
    const int step0  = kidx * 41 + (kidx < 38 ? kidx : 38);

    // ---- cp.async issue mapping ----
    const int am  = tid & 127;          // A row (m)
    const int ac0 = (tid >> 7) * 2;     // chunk base: 0 or 2 (16B chunks)
    const int bk  = tid >> 3;           // B raw row (k) 0..31
    const int bc0 = tid & 7;            // B chunk base
    const uint16_t* srcA0 = g_xh + (size_t)am * K_TOTAL + (size_t)step0 * 32 + ac0 * 8;
    const float*    srcB0 = W + ((size_t)step0 * 32 + bk) * D_DIM + ncol0;

    const uint32_t a_sw = ((uint32_t)(am & 3)) << 4;   // 2-bit swizzle, 64B rows
    auto issue = [&](int s) {
        // A f16 tile -> fA[s & 3]  (compact 64B rows)
        const uint32_t fa = sb + FA_BASE + (s & 3) * FA_STAGE + am * 64;
        #pragma unroll
        for (int i = 0; i < 2; i++)
            cp16(fa + (((ac0 + i) << 4) ^ a_sw), srcA0 + (size_t)s * 32 + i * 8);
        // B raw fp32 -> rawB[s % 3]  (512B rows, 32 chunks)
        const uint32_t rb = sb + RAWB_BASE + (s % 3) * RAWB_STAGE;
        const float* sB = srcB0 + (size_t)s * 32 * D_DIM;
        #pragma unroll
        for (int i = 0; i < 4; i++) {
            int cb = bc0 + 8 * i;
            cp16(rb + bk * 512 + ((cb ^ (bk & 7)) << 4), sB + cb * 4);
        }
    };

    // convB mapping: warp handles 4 k-rows (cbk0..cbk0+3), lane = one chunk
    const int cbk0 = wid * 4;

    // ---- ldmatrix address constants ----
    const int mw = wid >> 2;          // 0..1  m-block of 64
    const int nw = wid & 3;           // 0..3  n-block of 32
    const int a_m  = mw * 64 + (lane & 7) + ((lane >> 3) & 1) * 8;
    const int a_kb = ((lane >> 4) & 1) * 16;
    const int b_k0 = (lane & 7) + ((lane >> 3) & 1) * 8;
    const int b_nb = nw * 64 + ((lane >> 4) & 1) * 16;

    const int gid = lane >> 2;
    const int tig = lane & 3;

    float acc[4][4][4];
    #pragma unroll
    for (int i = 0; i < 4; i++)
        #pragma unroll
        for (int j = 0; j < 4; j++)
            #pragma unroll
            for (int q = 0; q < 4; q++) acc[i][j][q] = 0.0f;

    // prologue: 3 stages in flight, convert B(0)
    issue(0); cp_commit();
    issue(1); cp_commit();
    issue(2); cp_commit();
    cp_wait2();                  // group 0 complete
    __syncthreads();
    {   // convB(0): rawB[0] -> fB[0]
        const char* rawB = smem + RAWB_BASE;
        char* fB = smem + FB_BASE;
        #pragma unroll
        for (int r = 0; r < 4; r++) {
            const int k  = cbk0 + r;
            const int sx = (k & 7) << 4;
            float4 v = *(const float4*)(rawB + k * 512 + ((lane << 4) ^ sx));
            uint32_t p01, p23;
            asm("cvt.rn.f16x2.f32 %0, %1, %2;" : "=r"(p01) : "f"(v.y), "f"(v.x));
            asm("cvt.rn.f16x2.f32 %0, %1, %2;" : "=r"(p23) : "f"(v.w), "f"(v.z));
            *(uint2*)(fB + k * 256 + ((lane * 8) ^ sx)) = make_uint2(p01, p23);
        }
    }

    for (int s = 0; s < nsteps; s++) {
        cp_wait1();              // groups <= s+1 complete (s+2 may be in flight)
        __syncthreads();         // convB(s) visible; raw slot s%3 readers done

        if (s + 3 < nsteps) issue(s + 3);
        cp_commit();             // always commit (keeps group accounting)

        const bool doNext = (s + 1 < nsteps);

        // ---- overlap region: MMA(s)  |||  convB(s+1) ----
        const uint32_t fAu = sb + FA_BASE + (s & 3) * FA_STAGE;
        const uint32_t fBu = sb + FB_BASE + (s & 1) * FB_STAGE;
        const char* rawBn = smem + RAWB_BASE + ((s + 1) % 3) * RAWB_STAGE;
        char* fBn = smem + FB_BASE + ((s + 1) & 1) * FB_STAGE;

        uint32_t aBase[4];
        #pragma unroll
        for (int mt = 0; mt < 4; mt++) {
            const int m = a_m + mt * 16;
            aBase[mt] = fAu + m * 64 + (a_kb ^ ((m & 3) << 4));
        }

        float4 braw[2];
        #pragma unroll
        for (int kk = 0; kk < 2; kk++) {
            // load raw B rows for conv while MMA block runs
            if (doNext) {
                #pragma unroll
                for (int r = 0; r < 2; r++) {
                    const int k  = cbk0 + kk * 2 + r;
                    const int sx = (k & 7) << 4;
                    braw[r] = *(const float4*)(rawBn + k * 512 + ((lane << 4) ^ sx));
                }
            }

            uint32_t ahi[4][4];
            #pragma unroll
            for (int mt = 0; mt < 4; mt++)
                ldsm_x4(ahi[mt], aBase[mt] ^ (kk << 5));

            const int kr = kk * 16 + b_k0;
            const uint32_t bBase = fBu + kr * 256 + (b_nb ^ ((kr & 7) << 4));
            #pragma unroll
            for (int p = 0; p < 2; p++) {
                uint32_t bhi[4];
                ldsm_x4_t(bhi, bBase ^ (p << 5));
                #pragma unroll
                for (int mt = 0; mt < 4; mt++) {
                    #pragma unroll
                    for (int tt = 0; tt < 2; tt++)
                        mma16816(acc[mt][p * 2 + tt], ahi[mt], &bhi[2 * tt]);
                }
            }

            // convert + store the raw B rows
            if (doNext) {
                #pragma unroll
                for (int r = 0; r < 2; r++) {
                    const int k  = cbk0 + kk * 2 + r;
                    const int sx = (k & 7) << 4;
                    uint32_t p01, p23;
                    asm("cvt.rn.f16x2.f32 %0, %1, %2;"
                        : "=r"(p01) : "f"(braw[r].y), "f"(braw[r].x));
                    asm("cvt.rn.f16x2.f32 %0, %1, %2;"
                        : "=r"(p23) : "f"(braw[r].w), "f"(braw[r].z));
                    *(uint2*)(fBn + k * 256 + ((lane * 8) ^ sx)) = make_uint2(p01, p23);
                }
            }
        }
    }

    // ---- epilogue: write partial tile ----
    #pragma unroll
    for (int mt = 0; mt < 4; mt++) {
        const int r0 = mw * 64 + mt * 16 + gid;
        #pragma unroll
        for (int j = 0; j < 4; j++) {
            const int col = ncol0 + nw * 32 + j * 8 + tig * 2;
            float* base0 = g_partial + ((size_t)(kidx * M_ROWS + r0) << 9) + col;
            *(float2*)base0 = make_float2(acc[mt][j][0], acc[mt][j][1]);
            *(float2*)(base0 + (8 << 9)) = make_float2(acc[mt][j][2], acc[mt][j][3]);
        }
    }
}

// ---------------------------------------------------------------------------
// Kernel 2: reduce 74 partials + bias -> e[128][512]  (float4 per thread)
// ---------------------------------------------------------------------------
__global__ __launch_bounds__(512)
void reduce_kernel(const float* __restrict__ b) {
    const int base = (blockIdx.x * 512 + threadIdx.x) * 4;   // 0..65532
    float4 s = *(const float4*)(b + (base & 511));
    const float* p = g_partial + base;
    #pragma unroll 2
    for (int k = 0; k < KSPLITS; k++) {
        float4 v = *(const float4*)(p + (size_t)k * (M_ROWS * D_DIM));
        s.x += v.x; s.y += v.y; s.z += v.z; s.w += v.w;
    }
    *(float4*)(g_e + base) = s;
}

// ---------------------------------------------------------------------------
// Kernel 3: d (+ fused w/label), float4 per thread
// ---------------------------------------------------------------------------
__global__ __launch_bounds__(512)
void dist_kernel(const int* __restrict__ y, float* __restrict__ out) {
    const int tid = threadIdx.x;
    const int bx  = blockIdx.x * 4 + (tid >> 7);   // 0..3071 = i*96 + j*3 + g
    const int c4  = (tid & 127) << 2;
    const int g   = bx % 3;
    const int j   = (bx / 3) & 31;
    const int i   = bx / 96;
    float4 ep = *(const float4*)(g_e + (j * 4) * D_DIM + c4);
    float4 eg = *(const float4*)(g_e + ((((i + j) & 31) * 4) + g + 1) * D_DIM + c4);
    float4 d;
    d.x = (ep.x - eg.x) * (ep.x - eg.x);
    d.y = (ep.y - eg.y) * (ep.y - eg.y);
    d.z = (ep.z - eg.z) * (ep.z - eg.z);
    d.w = (ep.w - eg.w) * (ep.w - eg.w);
    *(float4*)(out + (size_t)bx * D_DIM + c4) = d;

    // fused w / label (first 24 blocks cover 12288 elements)
    if (blockIdx.x < 24) {
        const int t = blockIdx.x * 512 + tid;
        if (t < W_ELEMS) {
            const int p = t % 3;
            const int a = (t / 3) % 3;
            const int jj = (t / 9) & 31;
            const int ii = t / 288;
            const int r = (ii + jj) & 31;
            out[W_OFF + t] = (y[jj * 4 + 1 + a] == y[r * 4 + 1 + p]) ? 1.0f : 0.0f;
        } else {
            const int u = t - W_ELEMS;
            const int p = u % 3;
            const int jj = (u / 3) & 31;
            const int ii = u / 96;
            const int r = (ii + jj) & 31;
            out[L_OFF + u] = (y[jj * 4] == y[r * 4 + 1 + p]) ? 1.0f : 0.0f;
        }
    }
}

// ---------------------------------------------------------------------------
// Launch
// ---------------------------------------------------------------------------
extern "C" void kernel_launch(void* const* d_in, const int* in_sizes, int n_in,
                              void* d_out, int out_size) {
    const float* x = (const float*)d_in[0];
    const int*   y = (const int*)d_in[1];
    const float* W = (const float*)d_in[2];
    const float* b = (const float*)d_in[3];
    float* out = (float*)d_out;

    static bool attr_set = false;
    if (!attr_set) {
        cudaFuncSetAttribute(gemm_split_kernel,
                             cudaFuncAttributeMaxDynamicSharedMemorySize,
                             SMEM_TOTAL);
        attr_set = true;
    }

    convx_kernel<<<(M_ROWS * K_TOTAL) / (256 * 8), 256>>>(x);
    gemm_split_kernel<<<KSPLITS * 4, 256, SMEM_TOTAL>>>(W);
    reduce_kernel<<<32, 512>>>(b);
    dist_kernel<<<768, 512>>>(y, out);
}

// round 13
// speedup vs baseline: 1.2510x; 1.2510x over previous
#include <cuda_runtime.h>
#include <cstdint>

// ---------------------------------------------------------------------------
// Problem constants
// ---------------------------------------------------------------------------
#define K_TOTAL   98304      // F = 3*256*128
#define KSPLITS   74
#define M_ROWS    128        // B*N = 32*4
#define D_DIM     512
#define N_TILE    256        // N per CTA (2 halves)

#define D_ELEMS   (32*32*3*512)        // 1572864
#define W_ELEMS   (32*32*3*3)          // 9216
#define L_ELEMS   (32*32*3)            // 3072
#define W_OFF     D_ELEMS
#define L_OFF     (D_ELEMS + W_ELEMS)

// smem: f16 A quad-buffer (cp.async), f16 B double-buffer (LDG->cvt->STS)
#define FA_STAGE   16384     // 128 rows x 128B, swizzle (m&7)<<4
#define FB_STAGE   16384     // 32 k-rows x 512B (256 f16), swizzle (k&7)<<4
#define FA_BASE    0
#define FB_BASE    (4 * FA_STAGE)                   // 65536
#define SMEM_TOTAL (FB_BASE + 2 * FB_STAGE)         // 98304 (96KB)

// ---------------------------------------------------------------------------
// Scratch (static __device__: no allocation allowed)
// ---------------------------------------------------------------------------
__device__ float    g_partial[(size_t)KSPLITS * M_ROWS * D_DIM]; // ~18.5 MB
__device__ float    g_e[M_ROWS * D_DIM];                         // 256 KB
__device__ uint16_t g_xh[(size_t)M_ROWS * K_TOTAL];              // 24 MB

// ---------------------------------------------------------------------------
// PTX helpers (sm_80-era: portable to sm_100 base target)
// ---------------------------------------------------------------------------
__device__ __forceinline__ uint32_t smem_u32(const void* p) {
    uint32_t a;
    asm("{ .reg .u64 t; cvta.to.shared.u64 t, %1; cvt.u32.u64 %0, t; }"
        : "=r"(a) : "l"(p));
    return a;
}

__device__ __forceinline__ void cp16(uint32_t dst, const void* src) {
    asm volatile("cp.async.cg.shared.global [%0], [%1], 16;"
                 :: "r"(dst), "l"(src) : "memory");
}
__device__ __forceinline__ void cp_commit() {
    asm volatile("cp.async.commit_group;" ::: "memory");
}
__device__ __forceinline__ void cp_wait2() {
    asm volatile("cp.async.wait_group 2;" ::: "memory");
}

__device__ __forceinline__ void ldsm_x4(uint32_t* r, uint32_t a) {
    asm volatile("ldmatrix.sync.aligned.m8n8.x4.shared.b16 {%0,%1,%2,%3}, [%4];"
                 : "=r"(r[0]), "=r"(r[1]), "=r"(r[2]), "=r"(r[3]) : "r"(a));
}
__device__ __forceinline__ void ldsm_x4_t(uint32_t* r, uint32_t a) {
    asm volatile("ldmatrix.sync.aligned.m8n8.x4.trans.shared.b16 {%0,%1,%2,%3}, [%4];"
                 : "=r"(r[0]), "=r"(r[1]), "=r"(r[2]), "=r"(r[3]) : "r"(a));
}

__device__ __forceinline__ void mma16816(float* c, const uint32_t* a,
                                         const uint32_t* b) {
    asm volatile(
        "mma.sync.aligned.m16n8k16.row.col.f32.f16.f16.f32 "
        "{%0,%1,%2,%3}, {%4,%5,%6,%7}, {%8,%9}, {%0,%1,%2,%3};"
        : "+f"(c[0]), "+f"(c[1]), "+f"(c[2]), "+f"(c[3])
        : "r"(a[0]), "r"(a[1]), "r"(a[2]), "r"(a[3]), "r"(b[0]), "r"(b[1]));
}

// ---------------------------------------------------------------------------
// Kernel 0: convert x fp32 -> f16 (hi only), streaming
// ---------------------------------------------------------------------------
__global__ __launch_bounds__(256)
void convx_kernel(const float* __restrict__ x) {
    const size_t base = ((size_t)blockIdx.x * 256 + threadIdx.x) * 8;
    #pragma unroll
    for (int h = 0; h < 2; h++) {
        const size_t i = base + h * 4;
        float4 v = __ldg((const float4*)(x + i));
        uint32_t h01, h23;
        asm("cvt.rn.f16x2.f32 %0, %1, %2;" : "=r"(h01) : "f"(v.y), "f"(v.x));
        asm("cvt.rn.f16x2.f32 %0, %1, %2;" : "=r"(h23) : "f"(v.w), "f"(v.z));
        *(uint2*)(g_xh + i) = make_uint2(h01, h23);
    }
}

// ---------------------------------------------------------------------------
// Kernel 1: split-K fp16 GEMM -> partial sums
// grid = 148 CTAs: blockIdx.x = kidx*2 + nhalf ; 512 threads
// W path: LDG.128 (stage s+2) -> regs -> cvt+STS (stage s+1) -> ldsm (s+2)
// A path: cp.async f16 from g_xh, ring-4
// ---------------------------------------------------------------------------
__global__ __launch_bounds__(512, 1)
void gemm_split_kernel(const float* __restrict__ W) {
    extern __shared__ char smem[];
    const uint32_t sb = smem_u32(smem);
    const int tid  = threadIdx.x;
    const int wid  = tid >> 5;
    const int lane = tid & 31;

    const int nhalf = blockIdx.x & 1;
    const int kidx  = blockIdx.x >> 1;
    const int ncol0 = nhalf * N_TILE;
    // distribute 3072 32-wide K-steps over 74 splits: 38 CTAs get 42, rest 41
    const int nsteps = 41 + (kidx < 38 ? 1 : 0);
    const int step0  = kidx * 41 + (kidx < 38 ? kidx : 38);

    // ---- A cp.async mapping: 1 cp16/thread/stage ----
    const int am  = tid & 127;          // A row (m)
    const int ac0 = tid >> 7;           // 0..3 chunk (8 f16 each)
    const uint16_t* srcA0 = g_xh + (size_t)am * K_TOTAL + (size_t)step0 * 32 + ac0 * 8;
    const uint32_t a_sw = ((uint32_t)(am & 7)) << 4;
    auto issueA = [&](int s) {
        const uint32_t fa = sb + FA_BASE + (s & 3) * FA_STAGE + am * 128;
        cp16(fa + ((ac0 * 16) ^ a_sw), srcA0 + (size_t)s * 32);
    };

    // ---- W direct-LDG mapping: warp handles k-rows cbk0, cbk0+1 ----
    const int cbk0 = wid * 2;
    // thread covers row cbk0+r, chunks cb = lane + j*32 (float4 each)
    const float* srcW0 = W + ((size_t)step0 * 32) * D_DIM + ncol0;

    // ---- ldmatrix address constants ----
    const int mw = wid >> 2;          // 0..3  m-block of 32
    const int nw = wid & 3;           // 0..3  n-block of 64
    const int a_m  = mw * 32 + (lane & 7) + ((lane >> 3) & 1) * 8;
    const int a_kb = ((lane >> 4) & 1) * 16;
    const int b_k0 = (lane & 7) + ((lane >> 3) & 1) * 8;
    const int b_nb = nw * 128 + ((lane >> 4) & 1) * 16;

    const int gid = lane >> 2;
    const int tig = lane & 3;

    float acc[2][8][4];
    #pragma unroll
    for (int i = 0; i < 2; i++)
        #pragma unroll
        for (int j = 0; j < 8; j++)
            #pragma unroll
            for (int q = 0; q < 4; q++) acc[i][j][q] = 0.0f;

    // ---- prologue ----
    issueA(0); cp_commit();
    issueA(1); cp_commit();
    issueA(2); cp_commit();

    // B(0): LDG -> cvt -> STS fB[0]
    {
        char* fB = smem + FB_BASE;
        #pragma unroll
        for (int r = 0; r < 2; r++) {
            const int k  = cbk0 + r;
            const int sx = (k & 7) << 4;
            const float* row = srcW0 + (size_t)k * D_DIM;
            #pragma unroll
            for (int j = 0; j < 2; j++) {
                const int cb = lane + j * 32;
                float4 v = __ldg((const float4*)(row + cb * 4));
                uint32_t p01, p23;
                asm("cvt.rn.f16x2.f32 %0, %1, %2;" : "=r"(p01) : "f"(v.y), "f"(v.x));
                asm("cvt.rn.f16x2.f32 %0, %1, %2;" : "=r"(p23) : "f"(v.w), "f"(v.z));
                *(uint2*)(fB + k * 512 + ((cb * 8) ^ sx)) = make_uint2(p01, p23);
            }
        }
    }
    // preload bregs with B(1)
    float4 breg[2][2];
    #pragma unroll
    for (int r = 0; r < 2; r++) {
        const int k = cbk0 + r;
        const float* row = srcW0 + ((size_t)32 + k) * D_DIM;
        #pragma unroll
        for (int j = 0; j < 2; j++)
            breg[r][j] = __ldg((const float4*)(row + (lane + j * 32) * 4));
    }

    for (int s = 0; s < nsteps; s++) {
        cp_wait2();              // fA group s complete (s+1, s+2 in flight)
        __syncthreads();         // fB(s) STS visible; fA[(s+3)&3] readers done

        if (s + 3 < nsteps) issueA(s + 3);
        cp_commit();             // always commit (keeps group accounting)

        const bool doNext = (s + 1 < nsteps);   // STS B(s+1) from bregs
        const bool doLoad = (s + 2 < nsteps);   // LDG B(s+2) into bregs

        const uint32_t fAu = sb + FA_BASE + (s & 3) * FA_STAGE;
        const uint32_t fBu = sb + FB_BASE + (s & 1) * FB_STAGE;
        char* fBn = smem + FB_BASE + ((s + 1) & 1) * FB_STAGE;
        const float* srcWn = srcW0 + ((size_t)(s + 2) * 32) * D_DIM;

        uint32_t aBase[2];
        #pragma unroll
        for (int mt = 0; mt < 2; mt++) {
            const int m = a_m + mt * 16;
            aBase[mt] = fAu + m * 128 + (a_kb ^ ((m & 7) << 4));
        }

        #pragma unroll
        for (int kk = 0; kk < 2; kk++) {
            // consume bregs row kk: cvt + STS B(s+1)
            if (doNext) {
                const int k  = cbk0 + kk;
                const int sx = (k & 7) << 4;
                #pragma unroll
                for (int j = 0; j < 2; j++) {
                    const int cb = lane + j * 32;
                    uint32_t p01, p23;
                    asm("cvt.rn.f16x2.f32 %0, %1, %2;"
                        : "=r"(p01) : "f"(breg[kk][j].y), "f"(breg[kk][j].x));
                    asm("cvt.rn.f16x2.f32 %0, %1, %2;"
                        : "=r"(p23) : "f"(breg[kk][j].w), "f"(breg[kk][j].z));
                    *(uint2*)(fBn + k * 512 + ((cb * 8) ^ sx)) = make_uint2(p01, p23);
                }
            }

            uint32_t ahi[2][4];
            #pragma unroll
            for (int mt = 0; mt < 2; mt++)
                ldsm_x4(ahi[mt], aBase[mt] ^ (kk << 5));

            const int kr = kk * 16 + b_k0;
            const uint32_t bBase = fBu + kr * 512 + (b_nb ^ ((kr & 7) << 4));
            #pragma unroll
            for (int p = 0; p < 4; p++) {
                uint32_t bhi[4];
                ldsm_x4_t(bhi, bBase ^ (p << 5));
                #pragma unroll
                for (int mt = 0; mt < 2; mt++) {
                    #pragma unroll
                    for (int tt = 0; tt < 2; tt++)
                        mma16816(acc[mt][p * 2 + tt], ahi[mt], &bhi[2 * tt]);
                }
            }

            // refill bregs row kk with B(s+2) (lands during stage s+1)
            if (doLoad) {
                const int k = cbk0 + kk;
                const float* row = srcWn + (size_t)k * D_DIM;
                #pragma unroll
                for (int j = 0; j < 2; j++)
                    breg[kk][j] = __ldg((const float4*)(row + (lane + j * 32) * 4));
            }
        }
    }

    // ---- epilogue: write partial tile ----
    #pragma unroll
    for (int mt = 0; mt < 2; mt++) {
        const int r0 = mw * 32 + mt * 16 + gid;
        #pragma unroll
        for (int nt = 0; nt < 8; nt++) {
            const int col = ncol0 + nw * 64 + nt * 8 + tig * 2;
            float* base0 = g_partial + ((size_t)(kidx * M_ROWS + r0) << 9) + col;
            *(float2*)base0 = make_float2(acc[mt][nt][0], acc[mt][nt][1]);
            *(float2*)(base0 + (8 << 9)) = make_float2(acc[mt][nt][2], acc[mt][nt][3]);
        }
    }
}

// ---------------------------------------------------------------------------
// Kernel 2: reduce 74 partials + bias -> e[128][512]  (float4 per thread)
// ---------------------------------------------------------------------------
__global__ __launch_bounds__(512)
void reduce_kernel(const float* __restrict__ b) {
    const int base = (blockIdx.x * 512 + threadIdx.x) * 4;   // 0..65532
    float4 s = *(const float4*)(b + (base & 511));
    const float* p = g_partial + base;
    #pragma unroll 2
    for (int k = 0; k < KSPLITS; k++) {
        float4 v = *(const float4*)(p + (size_t)k * (M_ROWS * D_DIM));
        s.x += v.x; s.y += v.y; s.z += v.z; s.w += v.w;
    }
    *(float4*)(g_e + base) = s;
}

// ---------------------------------------------------------------------------
// Kernel 3: d (+ fused w/label), float4 per thread
// ---------------------------------------------------------------------------
__global__ __launch_bounds__(512)
void dist_kernel(const int* __restrict__ y, float* __restrict__ out) {
    const int tid = threadIdx.x;
    const int bx  = blockIdx.x * 4 + (tid >> 7);   // 0..3071 = i*96 + j*3 + g
    const int c4  = (tid & 127) << 2;
    const int g   = bx % 3;
    const int j   = (bx / 3) & 31;
    const int i   = bx / 96;
    float4 ep = *(const float4*)(g_e + (j * 4) * D_DIM + c4);
    float4 eg = *(const float4*)(g_e + ((((i + j) & 31) * 4) + g + 1) * D_DIM + c4);
    float4 d;
    d.x = (ep.x - eg.x) * (ep.x - eg.x);
    d.y = (ep.y - eg.y) * (ep.y - eg.y);
    d.z = (ep.z - eg.z) * (ep.z - eg.z);
    d.w = (ep.w - eg.w) * (ep.w - eg.w);
    *(float4*)(out + (size_t)bx * D_DIM + c4) = d;

    // fused w / label (first 24 blocks cover 12288 elements)
    if (blockIdx.x < 24) {
        const int t = blockIdx.x * 512 + tid;
        if (t < W_ELEMS) {
            const int p = t % 3;
            const int a = (t / 3) % 3;
            const int jj = (t / 9) & 31;
            const int ii = t / 288;
            const int r = (ii + jj) & 31;
            out[W_OFF + t] = (y[jj * 4 + 1 + a] == y[r * 4 + 1 + p]) ? 1.0f : 0.0f;
        } else {
            const int u = t - W_ELEMS;
            const int p = u % 3;
            const int jj = (u / 3) & 31;
            const int ii = u / 96;
            const int r = (ii + jj) & 31;
            out[L_OFF + u] = (y[jj * 4] == y[r * 4 + 1 + p]) ? 1.0f : 0.0f;
        }
    }
}

// ---------------------------------------------------------------------------
// Launch
// ---------------------------------------------------------------------------
extern "C" void kernel_launch(void* const* d_in, const int* in_sizes, int n_in,
                              void* d_out, int out_size) {
    const float* x = (const float*)d_in[0];
    const int*   y = (const int*)d_in[1];
    const float* W = (const float*)d_in[2];
    const float* b = (const float*)d_in[3];
    float* out = (float*)d_out;

    static bool attr_set = false;
    if (!attr_set) {
        cudaFuncSetAttribute(gemm_split_kernel,
                             cudaFuncAttributeMaxDynamicSharedMemorySize,
                             SMEM_TOTAL);
        attr_set = true;
    }

    convx_kernel<<<(M_ROWS * K_TOTAL) / (256 * 8), 256>>>(x);
    gemm_split_kernel<<<KSPLITS * 2, 512, SMEM_TOTAL>>>(W);
    reduce_kernel<<<32, 512>>>(b);
    dist_kernel<<<768, 512>>>(y, out);
}